// round 6
// baseline (speedup 1.0000x reference)
#include <cuda_runtime.h>
#include <cuda_bf16.h>
#include <math.h>

#define N_TOK 2048
#define DM 256
#define PWY 4096
#define KSEL 4
#define NE 16
#define HMAX 1280
#define NPAIR (N_TOK*KSEL)

typedef unsigned long long u64;
typedef unsigned int uint32;

#define MMA_BF16(d, a0,a1,a2,a3, b0,b1) \
  asm volatile("mma.sync.aligned.m16n8k16.row.col.f32.bf16.bf16.f32 " \
    "{%0,%1,%2,%3}, {%4,%5,%6,%7}, {%8,%9}, {%0,%1,%2,%3};" \
    : "+f"(d[0]),"+f"(d[1]),"+f"(d[2]),"+f"(d[3]) \
    : "r"(a0),"r"(a1),"r"(a2),"r"(a3),"r"(b0),"r"(b1))

// ---------------- device scratch (static, no allocation) ----------------
__device__ float g_h1[N_TOK*256];
__device__ float g_h2[N_TOK*128];
__device__ float g_scores[N_TOK*PWY];
__device__ float g_freq[PWY];
__device__ int   g_topidx[NPAIR];
__device__ float g_topval[NPAIR];
__device__ int   g_cnt[3*NE];
__device__ int   g_list[3*NE*NPAIR];
__device__ float g_pre0[NPAIR*DM];     // pre gemm output (pre-LN)
__device__ float g_xpre[NPAIR*DM];
__device__ float g_xmid[(size_t)NPAIR*HMAX];
__device__ float g_xmlp[NPAIR*DM];
__device__ float g_post0[NPAIR*DM];    // post gemm output (pre-LN/scatter)
// bf16 hi/lo transposed weights: WT[n][k]
__device__ __nv_bfloat16 g_rw1h[256*256],  g_rw1l[256*256];
__device__ __nv_bfloat16 g_rw2h[128*256],  g_rw2l[128*256];
__device__ __nv_bfloat16 g_rw3h[PWY*128],  g_rw3l[PWY*128];
__device__ __nv_bfloat16 g_pwh[NE*DM*DM],  g_pwl[NE*DM*DM];
__device__ __nv_bfloat16 g_m1h[NE*HMAX*DM], g_m1l[NE*HMAX*DM];
__device__ __nv_bfloat16 g_m2h[NE*DM*HMAX], g_m2l[NE*DM*HMAX];
__device__ __nv_bfloat16 g_qwh[NE*DM*DM],  g_qwl[NE*DM*DM];

__device__ __forceinline__ float geluf(float v){
    return 0.5f*v*(1.0f+erff(v*0.70710678118654752f));
}

__device__ __forceinline__ void cvt4(float4 v, uint2& h, uint2& l){
    __nv_bfloat16 h0=__float2bfloat16(v.x), h1=__float2bfloat16(v.y);
    __nv_bfloat16 h2=__float2bfloat16(v.z), h3=__float2bfloat16(v.w);
    __nv_bfloat162 p0(h0,h1), p1(h2,h3);
    h.x = *(uint32*)&p0; h.y = *(uint32*)&p1;
    __nv_bfloat16 l0=__float2bfloat16(v.x-__bfloat162float(h0));
    __nv_bfloat16 l1=__float2bfloat16(v.y-__bfloat162float(h1));
    __nv_bfloat16 l2=__float2bfloat16(v.z-__bfloat162float(h2));
    __nv_bfloat16 l3=__float2bfloat16(v.w-__bfloat162float(h3));
    __nv_bfloat162 q0(l0,l1), q1(l2,l3);
    l.x = *(uint32*)&q0; l.y = *(uint32*)&q1;
}

// ---------------- weight convert + transpose: W[R][C] fp32 -> WT[C][R] bf16 hi/lo ----------------
__global__ __launch_bounds__(256) void convt(
    const float* __restrict__ W, __nv_bfloat16* __restrict__ Th,
    __nv_bfloat16* __restrict__ Tl, int R, int C,
    long long wstride, long long tstride)
{
    int e = blockIdx.z;
    __shared__ float tile[32][33];
    int c0 = blockIdx.x*32, r0 = blockIdx.y*32;
    const float* Win = W + (size_t)e*wstride;
    int tx = threadIdx.x & 31, ty = threadIdx.x >> 5;   // 32 x 8
    for (int i=0;i<32;i+=8)
        tile[ty+i][tx] = Win[(size_t)(r0+ty+i)*C + c0+tx];
    __syncthreads();
    __nv_bfloat16* oh = Th + (size_t)e*tstride;
    __nv_bfloat16* ol = Tl + (size_t)e*tstride;
    for (int i=0;i<32;i+=8){
        float v = tile[tx][ty+i];
        __nv_bfloat16 h = __float2bfloat16(v);
        oh[(size_t)(c0+ty+i)*R + r0+tx] = h;
        ol[(size_t)(c0+ty+i)*R + r0+tx] = __float2bfloat16(v - __bfloat162float(h));
    }
}

// ---------------- bf16 split-precision tensor-core GEMM: 128x128 tile ----------------
// A fp32 rows (gathered via g_list when listoff>=0; row index = pair>>ashift).
// WT bf16 hi/lo [n][Kw] per expert. C = A*W + bias.
// act: 0 none, 1 gelu always, 3 gelu/relu by expert parity.
__global__ __launch_bounds__(256,2) void gemm_bf16(
    const float* __restrict__ A, int lda,
    const __nv_bfloat16* __restrict__ Wth, const __nv_bfloat16* __restrict__ Wtl,
    int Kw, long long wse,
    const float* __restrict__ bias, int bse,
    float* __restrict__ Cout, int ldc,
    int Kfix, int kvar, int nvar, int act, int listoff, int ashift)
{
    int e = blockIdx.z;
    int hid = DM*(2 + (e>>2));
    int K = kvar ? hid : Kfix;
    int n0 = blockIdx.x*128;
    if (nvar && n0 >= hid) return;
    int m0 = blockIdx.y*128;
    const int* list = 0; int cnt = 0;
    if (listoff >= 0){
        cnt = g_cnt[listoff+e];
        if (m0 >= cnt) return;
        list = g_list + (size_t)(listoff+e)*NPAIR;
    }
    __shared__ int pairs[128];
    __shared__ __nv_bfloat16 Ah[128][40], Al[128][40];
    __shared__ __nv_bfloat16 Bh[128][40], Bl[128][40];
    int tid = threadIdx.x;
    if (tid < 128)
        pairs[tid] = (listoff>=0) ? ((m0+tid < cnt) ? list[m0+tid] : -1) : (m0+tid);
    __syncthreads();

    int arow = tid>>1, akb = (tid&1)*16;
    int prA = pairs[arow];
    const float* Arow = (prA>=0) ? (A + (size_t)(prA>>ashift)*lda) : 0;
    const __nv_bfloat16* WThp = Wth + (size_t)e*wse + (size_t)(n0+arow)*Kw;
    const __nv_bfloat16* WTlp = Wtl + (size_t)e*wse + (size_t)(n0+arow)*Kw;

    int lane = tid & 31, wid = tid >> 5;
    int wm = wid >> 2, wn = wid & 3;
    int qr = lane >> 2, qc = lane & 3;

    float acc[4][4][4];
#pragma unroll
    for (int i=0;i<4;i++)
#pragma unroll
    for (int j=0;j<4;j++)
#pragma unroll
    for (int q=0;q<4;q++) acc[i][j][q]=0.f;

    int nchunks = K/32;
    for (int c=0;c<nchunks;c++){
        __syncthreads();
        {
            float4 v[4];
            const float* ap = Arow ? (Arow + c*32 + akb) : 0;
#pragma unroll
            for (int j=0;j<4;j++) v[j] = ap ? *(const float4*)(ap + j*4) : make_float4(0.f,0.f,0.f,0.f);
#pragma unroll
            for (int j=0;j<4;j++){
                uint2 h,l; cvt4(v[j], h, l);
                *(uint2*)&Ah[arow][akb + j*4] = h;
                *(uint2*)&Al[arow][akb + j*4] = l;
            }
        }
        {
            uint4 bh0 = *(const uint4*)(WThp + c*32 + akb);
            uint4 bh1 = *(const uint4*)(WThp + c*32 + akb + 8);
            uint4 bl0 = *(const uint4*)(WTlp + c*32 + akb);
            uint4 bl1 = *(const uint4*)(WTlp + c*32 + akb + 8);
            *(uint2*)&Bh[arow][akb+0]  = make_uint2(bh0.x, bh0.y);
            *(uint2*)&Bh[arow][akb+4]  = make_uint2(bh0.z, bh0.w);
            *(uint2*)&Bh[arow][akb+8]  = make_uint2(bh1.x, bh1.y);
            *(uint2*)&Bh[arow][akb+12] = make_uint2(bh1.z, bh1.w);
            *(uint2*)&Bl[arow][akb+0]  = make_uint2(bl0.x, bl0.y);
            *(uint2*)&Bl[arow][akb+4]  = make_uint2(bl0.z, bl0.w);
            *(uint2*)&Bl[arow][akb+8]  = make_uint2(bl1.x, bl1.y);
            *(uint2*)&Bl[arow][akb+12] = make_uint2(bl1.z, bl1.w);
        }
        __syncthreads();
#pragma unroll
        for (int k16=0;k16<32;k16+=16){
            uint32 bh[4][2], bl[4][2];
#pragma unroll
            for (int nf=0;nf<4;nf++){
                int n = wn*32 + nf*8 + qr;
                bh[nf][0] = *(const uint32*)&Bh[n][k16 + qc*2];
                bh[nf][1] = *(const uint32*)&Bh[n][k16 + qc*2 + 8];
                bl[nf][0] = *(const uint32*)&Bl[n][k16 + qc*2];
                bl[nf][1] = *(const uint32*)&Bl[n][k16 + qc*2 + 8];
            }
#pragma unroll
            for (int mf=0;mf<4;mf++){
                int m = wm*64 + mf*16 + qr;
                uint32 ah0 = *(const uint32*)&Ah[m][k16 + qc*2];
                uint32 ah1 = *(const uint32*)&Ah[m+8][k16 + qc*2];
                uint32 ah2 = *(const uint32*)&Ah[m][k16 + qc*2 + 8];
                uint32 ah3 = *(const uint32*)&Ah[m+8][k16 + qc*2 + 8];
                uint32 al0 = *(const uint32*)&Al[m][k16 + qc*2];
                uint32 al1 = *(const uint32*)&Al[m+8][k16 + qc*2];
                uint32 al2 = *(const uint32*)&Al[m][k16 + qc*2 + 8];
                uint32 al3 = *(const uint32*)&Al[m+8][k16 + qc*2 + 8];
#pragma unroll
                for (int nf=0;nf<4;nf++){
                    MMA_BF16(acc[mf][nf], ah0,ah1,ah2,ah3, bh[nf][0],bh[nf][1]);
                    MMA_BF16(acc[mf][nf], ah0,ah1,ah2,ah3, bl[nf][0],bl[nf][1]);
                    MMA_BF16(acc[mf][nf], al0,al1,al2,al3, bh[nf][0],bh[nf][1]);
                }
            }
        }
    }

    bool relu_e = (act==3) && (e&1);
#pragma unroll
    for (int mf=0;mf<4;mf++){
        int r0 = wm*64 + mf*16 + qr;
        int r1 = r0 + 8;
        int pr0 = pairs[r0], pr1 = pairs[r1];
#pragma unroll
        for (int nf=0;nf<4;nf++){
            int n = n0 + wn*32 + nf*8 + qc*2;
            float b0 = bias[(size_t)e*bse + n];
            float b1 = bias[(size_t)e*bse + n + 1];
            float v00 = acc[mf][nf][0] + b0, v01 = acc[mf][nf][1] + b1;
            float v10 = acc[mf][nf][2] + b0, v11 = acc[mf][nf][3] + b1;
            if (act==1){
                v00=geluf(v00); v01=geluf(v01); v10=geluf(v10); v11=geluf(v11);
            } else if (act==3){
                if (relu_e){
                    v00=fmaxf(v00,0.f); v01=fmaxf(v01,0.f);
                    v10=fmaxf(v10,0.f); v11=fmaxf(v11,0.f);
                } else {
                    v00=geluf(v00); v01=geluf(v01);
                    v10=geluf(v10); v11=geluf(v11);
                }
            }
            if (pr0>=0) *(float2*)&Cout[(size_t)pr0*ldc + n] = make_float2(v00,v01);
            if (pr1>=0) *(float2*)&Cout[(size_t)pr1*ldc + n] = make_float2(v10,v11);
        }
    }
}

// ---------------- pre epilogue: LN + act per pair row ----------------
__global__ __launch_bounds__(256) void epil_pre(
    const float* __restrict__ pg, const float* __restrict__ pbb)
{
    int i = blockIdx.x*8 + (threadIdx.x>>5);
    int lane = threadIdx.x & 31;
    int e = g_topidx[i] >> 8;
    const float* row = g_pre0 + (size_t)i*DM;
    float y[8];
    float4 v0 = *(const float4*)&row[lane*8];
    float4 v1 = *(const float4*)&row[lane*8+4];
    y[0]=v0.x;y[1]=v0.y;y[2]=v0.z;y[3]=v0.w;y[4]=v1.x;y[5]=v1.y;y[6]=v1.z;y[7]=v1.w;
    float s = y[0]+y[1]+y[2]+y[3]+y[4]+y[5]+y[6]+y[7];
#pragma unroll
    for (int m=16;m>0;m>>=1) s += __shfl_xor_sync(0xffffffffu, s, m, 32);
    float mu = s * (1.0f/DM);
    float ss = 0.f;
#pragma unroll
    for (int j=0;j<8;j++){ float d=y[j]-mu; ss += d*d; }
#pragma unroll
    for (int m=16;m>0;m>>=1) ss += __shfl_xor_sync(0xffffffffu, ss, m, 32);
    float rstd = rsqrtf(ss*(1.0f/DM) + 1e-5f);
    int actm = e % 3;
    float o[8];
#pragma unroll
    for (int j=0;j<8;j++){
        int c = lane*8 + j;
        float v = (y[j]-mu)*rstd*pg[e*DM+c] + pbb[e*DM+c];
        o[j] = (actm==0) ? geluf(v) : (actm==1) ? fmaxf(v,0.f) : tanhf(v);
    }
    float* orow = g_xpre + (size_t)i*DM;
    *(float4*)&orow[lane*8]   = make_float4(o[0],o[1],o[2],o[3]);
    *(float4*)&orow[lane*8+4] = make_float4(o[4],o[5],o[6],o[7]);
}

// ---------------- post epilogue: optional LN + weighted scatter ----------------
__global__ __launch_bounds__(256) void epil_post(
    const float* __restrict__ qg, const float* __restrict__ qbb,
    float* __restrict__ out_y)
{
    int i = blockIdx.x*8 + (threadIdx.x>>5);
    int lane = threadIdx.x & 31;
    int e = g_topidx[i] & 15;
    const float* row = g_post0 + (size_t)i*DM;
    float y[8];
    float4 v0 = *(const float4*)&row[lane*8];
    float4 v1 = *(const float4*)&row[lane*8+4];
    y[0]=v0.x;y[1]=v0.y;y[2]=v0.z;y[3]=v0.w;y[4]=v1.x;y[5]=v1.y;y[6]=v1.z;y[7]=v1.w;
    if ((e & 1) == 0){
        float s = y[0]+y[1]+y[2]+y[3]+y[4]+y[5]+y[6]+y[7];
#pragma unroll
        for (int m=16;m>0;m>>=1) s += __shfl_xor_sync(0xffffffffu, s, m, 32);
        float mu = s * (1.0f/DM);
        float ss = 0.f;
#pragma unroll
        for (int j=0;j<8;j++){ float d=y[j]-mu; ss += d*d; }
#pragma unroll
        for (int m=16;m>0;m>>=1) ss += __shfl_xor_sync(0xffffffffu, ss, m, 32);
        float rstd = rsqrtf(ss*(1.0f/DM) + 1e-5f);
#pragma unroll
        for (int j=0;j<8;j++){
            int c = lane*8 + j;
            y[j] = (y[j]-mu)*rstd*qg[e*DM+c] + qbb[e*DM+c];
        }
    }
    float w = g_topval[i];
    int tok = i >> 2;
#pragma unroll
    for (int j=0;j<8;j++)
        atomicAdd(&out_y[(size_t)tok*DM + lane*8 + j], y[j]*w);
}

// ---------------- softmax + topk + pathway_weights + probs writeback ----------------
__global__ __launch_bounds__(256) void softmax_topk(
    const float* __restrict__ temp, float* __restrict__ pwout)
{
    __shared__ float s[PWY];
    __shared__ float rv[256*4];
    __shared__ int   ri[256*4];
    __shared__ float red1[256];
    __shared__ float red2[256];
    __shared__ float pv[KSEL];
    int n = blockIdx.x, tid = threadIdx.x;
    float* srow = g_scores + (size_t)n*PWY;
    for (int i=0;i<4;i++){
        int idx = i*1024 + tid*4;
        *(float4*)&s[idx] = *(const float4*)&srow[idx];
    }
    __syncthreads();
    float invt = 1.0f/temp[0];

    float tv[4] = {-INFINITY,-INFINITY,-INFINITY,-INFINITY};
    int tix[4] = {PWY,PWY,PWY,PWY};
    float lm = -INFINITY;
#pragma unroll
    for (int i=0;i<16;i++){
        int j = tid + i*256;
        float v = s[j];
        lm = fmaxf(lm, v);
        if (v > tv[3] || (v == tv[3] && j < tix[3])){
            tv[3]=v; tix[3]=j;
#pragma unroll
            for (int q=3;q>0;q--){
                if (tv[q] > tv[q-1] || (tv[q]==tv[q-1] && tix[q] < tix[q-1])){
                    float tmv=tv[q]; tv[q]=tv[q-1]; tv[q-1]=tmv;
                    int tmi=tix[q]; tix[q]=tix[q-1]; tix[q-1]=tmi;
                }
            }
        }
    }
    red1[tid]=lm; __syncthreads();
    for (int off=128;off>0;off>>=1){ if(tid<off) red1[tid]=fmaxf(red1[tid],red1[tid+off]); __syncthreads(); }
    float m0 = red1[0]; __syncthreads();

    float f[16]; float ls0=0.f, lst=0.f;
#pragma unroll
    for (int i=0;i<16;i++){
        int j = tid + i*256;
        float d = s[j]-m0;
        float e0 = __expf(d);
        f[i]=e0; ls0+=e0;
        lst += __expf(d*invt);
    }
    red1[tid]=ls0; red2[tid]=lst; __syncthreads();
    for (int off=128;off>0;off>>=1){
        if(tid<off){ red1[tid]+=red1[tid+off]; red2[tid]+=red2[tid+off]; }
        __syncthreads();
    }
    float inv0 = 1.0f/red1[0];
    float invsumt = 1.0f/red2[0];
    __syncthreads();

#pragma unroll
    for (int i=0;i<16;i++) srow[tid + i*256] = f[i]*inv0;

#pragma unroll
    for (int q=0;q<4;q++){ rv[tid*4+q]=tv[q]; ri[tid*4+q]=tix[q]; }
    __syncthreads();
    for (int off=128;off>0;off>>=1){
        if (tid < off){
            float a0[4], b0[4]; int ai[4], bi[4];
#pragma unroll
            for (int q=0;q<4;q++){
                a0[q]=rv[tid*4+q]; ai[q]=ri[tid*4+q];
                b0[q]=rv[(tid+off)*4+q]; bi[q]=ri[(tid+off)*4+q];
            }
            int ia=0, ib=0;
            float ov[4]; int oi[4];
#pragma unroll
            for (int q=0;q<4;q++){
                bool ta = (a0[ia] > b0[ib]) || (a0[ia]==b0[ib] && ai[ia] < bi[ib]);
                if (ta){ ov[q]=a0[ia]; oi[q]=ai[ia]; ia++; }
                else   { ov[q]=b0[ib]; oi[q]=bi[ib]; ib++; }
            }
#pragma unroll
            for (int q=0;q<4;q++){ rv[tid*4+q]=ov[q]; ri[tid*4+q]=oi[q]; }
        }
        __syncthreads();
    }

    if (tid < KSEL){
        int se = ri[tid];
        float p = __expf((s[se]-m0)*invt)*invsumt;
        pv[tid]=p;
        g_topidx[n*KSEL+tid]=se;
        g_topval[n*KSEL+tid]=p;
    }
    __syncthreads();
    float invps = 1.0f/(pv[0]+pv[1]+pv[2]+pv[3] + 1e-8f);
    int s0=ri[0], s1=ri[1], s2=ri[2], s3=ri[3];
    float w0=pv[0]*invps, w1=pv[1]*invps, w2=pv[2]*invps, w3=pv[3]*invps;
    float* prow = pwout + (size_t)n*PWY;
    for (int i=0;i<16;i++){
        int j = tid + i*256;
        float v = 0.f;
        if (j==s0) v=w0; else if (j==s1) v=w1; else if (j==s2) v=w2; else if (j==s3) v=w3;
        prow[j]=v;
    }
}

// ---------------- freq: pure column sums of probs ----------------
__global__ __launch_bounds__(256) void freq_partial()
{
    int p = blockIdx.x*256 + threadIdx.x;
    int nbeg = blockIdx.y*256;
    float acc = 0.f;
    for (int n=nbeg; n<nbeg+256; n++)
        acc += g_scores[(size_t)n*PWY + p];
    atomicAdd(&g_freq[p], acc);
}

__global__ __launch_bounds__(256) void glbl_loss_kernel(float* __restrict__ out)
{
    __shared__ float red[256];
    int tid = threadIdx.x;
    const float invN = 1.0f/(float)N_TOK;
    float lsum = 0.f;
    for (int i=0;i<PWY/256;i++) lsum += g_freq[tid+i*256]*invN;
    red[tid]=lsum; __syncthreads();
    for (int off=128;off>0;off>>=1){ if(tid<off) red[tid]+=red[tid+off]; __syncthreads(); }
    float mean = red[0]/(float)PWY; __syncthreads();
    float lss = 0.f;
    for (int i=0;i<PWY/256;i++){
        float d = g_freq[tid+i*256]*invN - mean;
        lss += d*d;
    }
    red[tid]=lss; __syncthreads();
    for (int off=128;off>0;off>>=1){ if(tid<off) red[tid]+=red[tid+off]; __syncthreads(); }
    if (tid==0) out[0] = (float)PWY * (red[0]/(float)(PWY-1));
}

// ---------------- routing lists ----------------
__global__ __launch_bounds__(256) void build_lists()
{
    int i = blockIdx.x*256 + threadIdx.x;
    if (i >= NPAIR) return;
    int idx = g_topidx[i];
    int pe = idx >> 8, rem = idx & 255;
    int me = rem >> 4, qe = rem & 15;
    int pos;
    pos = atomicAdd(&g_cnt[pe], 1);         g_list[pe*NPAIR + pos] = i;
    pos = atomicAdd(&g_cnt[NE+me], 1);      g_list[(NE+me)*NPAIR + pos] = i;
    pos = atomicAdd(&g_cnt[2*NE+qe], 1);    g_list[(2*NE+qe)*NPAIR + pos] = i;
}

// ---------------- host launch ----------------
extern "C" void kernel_launch(void* const* d_in, const int* in_sizes, int n_in,
                              void* d_out, int out_size)
{
    const float* x   = (const float*)d_in[0];
    const float* rw1 = (const float*)d_in[1];
    const float* rb1 = (const float*)d_in[2];
    const float* rw2 = (const float*)d_in[3];
    const float* rb2 = (const float*)d_in[4];
    const float* rw3 = (const float*)d_in[5];
    const float* rb3 = (const float*)d_in[6];
    const float* temp= (const float*)d_in[7];
    const float* pw  = (const float*)d_in[8];
    const float* pb  = (const float*)d_in[9];
    const float* pg  = (const float*)d_in[10];
    const float* pbb = (const float*)d_in[11];
    const float* mw1 = (const float*)d_in[12];
    const float* mb1 = (const float*)d_in[13];
    const float* mw2 = (const float*)d_in[14];
    const float* mb2 = (const float*)d_in[15];
    const float* qw  = (const float*)d_in[16];
    const float* qb  = (const float*)d_in[17];
    const float* qg  = (const float*)d_in[18];
    const float* qbb = (const float*)d_in[19];

    float* out      = (float*)d_out;
    float* out_y    = out;
    float* out_loss = out + N_TOK*DM;
    float* out_pw   = out + N_TOK*DM + 1;

    void* p;
    cudaGetSymbolAddress(&p, g_h1);     float* h1 = (float*)p;
    cudaGetSymbolAddress(&p, g_h2);     float* h2 = (float*)p;
    cudaGetSymbolAddress(&p, g_scores); float* scores = (float*)p;
    cudaGetSymbolAddress(&p, g_freq);   float* freqp = (float*)p;
    cudaGetSymbolAddress(&p, g_cnt);    int*   cntp = (int*)p;
    cudaGetSymbolAddress(&p, g_pre0);   float* pre0 = (float*)p;
    cudaGetSymbolAddress(&p, g_xpre);   float* xpre = (float*)p;
    cudaGetSymbolAddress(&p, g_xmid);   float* xmid = (float*)p;
    cudaGetSymbolAddress(&p, g_xmlp);   float* xmlp = (float*)p;
    cudaGetSymbolAddress(&p, g_post0);  float* post0 = (float*)p;
    cudaGetSymbolAddress(&p, g_rw1h);   __nv_bfloat16* rw1h = (__nv_bfloat16*)p;
    cudaGetSymbolAddress(&p, g_rw1l);   __nv_bfloat16* rw1l = (__nv_bfloat16*)p;
    cudaGetSymbolAddress(&p, g_rw2h);   __nv_bfloat16* rw2h = (__nv_bfloat16*)p;
    cudaGetSymbolAddress(&p, g_rw2l);   __nv_bfloat16* rw2l = (__nv_bfloat16*)p;
    cudaGetSymbolAddress(&p, g_rw3h);   __nv_bfloat16* rw3h = (__nv_bfloat16*)p;
    cudaGetSymbolAddress(&p, g_rw3l);   __nv_bfloat16* rw3l = (__nv_bfloat16*)p;
    cudaGetSymbolAddress(&p, g_pwh);    __nv_bfloat16* pwh = (__nv_bfloat16*)p;
    cudaGetSymbolAddress(&p, g_pwl);    __nv_bfloat16* pwl = (__nv_bfloat16*)p;
    cudaGetSymbolAddress(&p, g_m1h);    __nv_bfloat16* m1h = (__nv_bfloat16*)p;
    cudaGetSymbolAddress(&p, g_m1l);    __nv_bfloat16* m1l = (__nv_bfloat16*)p;
    cudaGetSymbolAddress(&p, g_m2h);    __nv_bfloat16* m2h = (__nv_bfloat16*)p;
    cudaGetSymbolAddress(&p, g_m2l);    __nv_bfloat16* m2l = (__nv_bfloat16*)p;
    cudaGetSymbolAddress(&p, g_qwh);    __nv_bfloat16* qwh = (__nv_bfloat16*)p;
    cudaGetSymbolAddress(&p, g_qwl);    __nv_bfloat16* qwl = (__nv_bfloat16*)p;

    cudaMemsetAsync(out_y, 0, (size_t)N_TOK*DM*sizeof(float), 0);
    cudaMemsetAsync(freqp, 0, PWY*sizeof(float), 0);
    cudaMemsetAsync(cntp,  0, 3*NE*sizeof(int), 0);

    // weight conversion + transpose (bf16 hi/lo)
    convt<<<dim3(256/32, 256/32, 1), 256>>>(rw1, rw1h, rw1l, 256, 256, 0LL, 0LL);
    convt<<<dim3(128/32, 256/32, 1), 256>>>(rw2, rw2h, rw2l, 256, 128, 0LL, 0LL);
    convt<<<dim3(PWY/32, 128/32, 1), 256>>>(rw3, rw3h, rw3l, 128, PWY, 0LL, 0LL);
    convt<<<dim3(DM/32, DM/32, NE), 256>>>(pw, pwh, pwl, DM, DM,
        (long long)DM*DM, (long long)DM*DM);
    convt<<<dim3(HMAX/32, DM/32, NE), 256>>>(mw1, m1h, m1l, DM, HMAX,
        (long long)DM*HMAX, (long long)HMAX*DM);
    convt<<<dim3(DM/32, HMAX/32, NE), 256>>>(mw2, m2h, m2l, HMAX, DM,
        (long long)HMAX*DM, (long long)DM*HMAX);
    convt<<<dim3(DM/32, DM/32, NE), 256>>>(qw, qwh, qwl, DM, DM,
        (long long)DM*DM, (long long)DM*DM);

    // router (all tensor-core)
    gemm_bf16<<<dim3(2, N_TOK/128, 1), 256>>>(
        x, DM, rw1h, rw1l, 256, 0LL, rb1, 0, h1, 256, 256, 0, 0, 1, -1, 0);
    gemm_bf16<<<dim3(1, N_TOK/128, 1), 256>>>(
        h1, 256, rw2h, rw2l, 256, 0LL, rb2, 0, h2, 128, 256, 0, 0, 1, -1, 0);
    gemm_bf16<<<dim3(PWY/128, N_TOK/128, 1), 256>>>(
        h2, 128, rw3h, rw3l, 128, 0LL, rb3, 0, scores, PWY, 128, 0, 0, 0, -1, 0);

    // softmax + topk + pathway weights + probs writeback
    softmax_topk<<<N_TOK, 256>>>(temp, out_pw);

    // GLBL loss
    freq_partial<<<dim3(PWY/256, N_TOK/256), 256>>>();
    glbl_loss_kernel<<<1, 256>>>(out_loss);

    // routing
    build_lists<<<NPAIR/256, 256>>>();

    // pre experts: tensor gemm -> LN epilogue
    gemm_bf16<<<dim3(DM/128, NPAIR/128, NE), 256>>>(
        x, DM, pwh, pwl, DM, (long long)DM*DM, pb, DM, pre0, DM,
        DM, 0, 0, 0, 0, 2);
    epil_pre<<<NPAIR/8, 256>>>(pg, pbb);

    // mlp experts
    gemm_bf16<<<dim3(HMAX/128, NPAIR/128, NE), 256>>>(
        xpre, DM, m1h, m1l, DM, (long long)HMAX*DM, mb1, HMAX, xmid, HMAX,
        DM, 0, 1, 3, NE, 0);
    gemm_bf16<<<dim3(DM/128, NPAIR/128, NE), 256>>>(
        xmid, HMAX, m2h, m2l, HMAX, (long long)DM*HMAX, mb2, DM, xmlp, DM,
        0, 1, 0, 0, NE, 0);

    // post experts: tensor gemm -> LN + scatter epilogue
    gemm_bf16<<<dim3(DM/128, NPAIR/128, NE), 256>>>(
        xmlp, DM, qwh, qwl, DM, (long long)DM*DM, qb, DM, post0, DM,
        DM, 0, 0, 0, 2*NE, 0);
    epil_post<<<NPAIR/8, 256>>>(qg, qbb, out_y);
}